// round 16
// baseline (speedup 1.0000x reference)
#include <cuda_runtime.h>
#include <cuda_bf16.h>
#include <cstdint>

#define B_ 16384
#define D_ 1536
#define H_ 12288
#define K_ 32
#define MARGIN 40
#define CAND 64
#define RPB 4                           // rows per rescore block

#define BM 128
#define BN 128
#define BK 64
#define STAGES 3
#define NT (D_ / BK)                    // 24 k-tiles
#define STAGE_BYTES (BM * 128 + BN * 128)   // 32 KB (A 16KB + B 16KB)

// ---------------- static scratch ----------------
__device__ __align__(256) __nv_bfloat16 g_Xbf[(size_t)B_ * D_];  // centered x, bf16
__device__ __align__(256) __nv_bfloat16 g_Wbf[(size_t)H_ * D_];  // W_enc, bf16
__device__ __align__(256) __nv_bfloat16 g_Pa[(size_t)B_ * H_];   // approx preact, bf16
__device__ __align__(256) float g_WdT[(size_t)H_ * D_];          // W_dec^T (H,D)
__device__ int   g_candIdx[B_ * CAND];
__device__ int   g_candCnt[B_];

// ---------------- helpers ----------------
static __device__ __forceinline__ uint32_t smem_u32(const void* p) {
    uint32_t a;
    asm("{ .reg .u64 t; cvta.to.shared.u64 t, %1; cvt.u32.u64 %0, t; }" : "=r"(a) : "l"(p));
    return a;
}
#define CP16(dst, src) \
    asm volatile("cp.async.cg.shared.global [%0], [%1], 16;" :: "r"(dst), "l"(src) : "memory")
#define CP_COMMIT() asm volatile("cp.async.commit_group;" ::: "memory")
#define CP_WAIT1()  asm volatile("cp.async.wait_group 1;" ::: "memory")

#define LDSM4(r0, r1, r2, r3, a) \
    asm volatile("ldmatrix.sync.aligned.m8n8.x4.shared.b16 {%0,%1,%2,%3}, [%4];" \
                 : "=r"(r0), "=r"(r1), "=r"(r2), "=r"(r3) : "r"(a))

#define MMA16816(c0, c1, c2, c3, a0, a1, a2, a3, b0, b1) \
    asm volatile("mma.sync.aligned.m16n8k16.row.col.f32.bf16.bf16.f32 " \
                 "{%0,%1,%2,%3},{%4,%5,%6,%7},{%8,%9},{%0,%1,%2,%3};" \
                 : "+f"(c0), "+f"(c1), "+f"(c2), "+f"(c3) \
                 : "r"(a0), "r"(a1), "r"(a2), "r"(a3), "r"(b0), "r"(b1))

// ---------------- prep: x_centered -> bf16 ----------------
__global__ void __launch_bounds__(384) prep_x(const float* __restrict__ x,
                                              const float* __restrict__ bd) {
    int t = threadIdx.x;                       // 384 = D_/4
    size_t base = (size_t)blockIdx.x * D_;
    float4 xv = ((const float4*)(x + base))[t];
    float4 bv = ((const float4*)bd)[t];
    __nv_bfloat162 p0 = __floats2bfloat162_rn(xv.x - bv.x, xv.y - bv.y);
    __nv_bfloat162 p1 = __floats2bfloat162_rn(xv.z - bv.z, xv.w - bv.w);
    uint2 o;
    o.x = *(uint32_t*)&p0;
    o.y = *(uint32_t*)&p1;
    ((uint2*)(g_Xbf + base))[t] = o;
}

// ---------------- prep: W_enc -> bf16 ----------------
__global__ void __launch_bounds__(384) prep_w(const float* __restrict__ W) {
    int t = threadIdx.x;
    size_t base = (size_t)blockIdx.x * D_;
    float4 wv = ((const float4*)(W + base))[t];
    __nv_bfloat162 p0 = __floats2bfloat162_rn(wv.x, wv.y);
    __nv_bfloat162 p1 = __floats2bfloat162_rn(wv.z, wv.w);
    uint2 o;
    o.x = *(uint32_t*)&p0;
    o.y = *(uint32_t*)&p1;
    ((uint2*)(g_Wbf + base))[t] = o;
}

// ---------------- prep: transpose W_dec (D,H) -> (H,D) ----------------
__global__ void __launch_bounds__(256) prep_transpose(const float* __restrict__ Wd) {
    __shared__ float t[32][33];
    int h0 = blockIdx.x * 32, d0 = blockIdx.y * 32;
    int x = threadIdx.x, y = threadIdx.y;
#pragma unroll
    for (int j = 0; j < 32; j += 8)
        t[y + j][x] = Wd[(size_t)(d0 + y + j) * H_ + h0 + x];
    __syncthreads();
#pragma unroll
    for (int j = 0; j < 32; j += 8)
        g_WdT[(size_t)(h0 + y + j) * D_ + d0 + x] = t[x][y + j];
}

// ---------------- encoder GEMM (mma.sync bf16): approx preact ----------------
__global__ void __launch_bounds__(256, 2) enc_gemm(const float* __restrict__ be) {
    extern __shared__ char smem[];
    const uint32_t sbase = smem_u32(smem);
    const int tid = threadIdx.x;
    const int bx = blockIdx.x;   // N tile (96)
    const int by = blockIdx.y;   // M tile (128)
    const int lane = tid & 31, w = tid >> 5;
    const int wm = (w >> 2) * 64;
    const int wn = (w & 3) * 32;

    const int grow = tid >> 1;
    const int half = tid & 1;
    const __nv_bfloat16* Agp = g_Xbf + (size_t)(by * BM + grow) * D_;
    const __nv_bfloat16* Bgp = g_Wbf + (size_t)(bx * BN + grow) * D_;
    uint32_t dstOff[4];
#pragma unroll
    for (int i = 0; i < 4; i++) {
        const int c = half * 4 + i;
        dstOff[i] = grow * 128 + (((c) ^ (grow & 7)) << 4);
    }
    const int srcC = half * 4;

    const int rAb = wm + (lane & 7) + ((lane >> 3) & 1) * 8;
    const int cAdd = lane >> 4;
    const int rBb = wn + ((lane >> 4) & 1) * 8 + (lane & 7);
    const int cBdd = (lane >> 3) & 1;

    float acc[4][4][4];
#pragma unroll
    for (int i = 0; i < 4; i++)
#pragma unroll
        for (int j = 0; j < 4; j++)
#pragma unroll
            for (int q = 0; q < 4; q++) acc[i][j][q] = 0.f;

#pragma unroll
    for (int s = 0; s < STAGES - 1; s++) {
        const uint32_t sA = sbase + s * STAGE_BYTES;
        const uint32_t sB = sA + BM * 128;
        const __nv_bfloat16* a = Agp + s * BK + srcC * 8;
        const __nv_bfloat16* b = Bgp + s * BK + srcC * 8;
#pragma unroll
        for (int i = 0; i < 4; i++) {
            CP16(sA + dstOff[i], a + i * 8);
            CP16(sB + dstOff[i], b + i * 8);
        }
        CP_COMMIT();
    }

    int slot = 0, wslot = STAGES - 1;
    for (int kt = 0; kt < NT; kt++) {
        CP_WAIT1();
        __syncthreads();

        if (kt + STAGES - 1 < NT) {
            const uint32_t sA = sbase + wslot * STAGE_BYTES;
            const uint32_t sB = sA + BM * 128;
            const __nv_bfloat16* a = Agp + (kt + STAGES - 1) * BK + srcC * 8;
            const __nv_bfloat16* b = Bgp + (kt + STAGES - 1) * BK + srcC * 8;
#pragma unroll
            for (int i = 0; i < 4; i++) {
                CP16(sA + dstOff[i], a + i * 8);
                CP16(sB + dstOff[i], b + i * 8);
            }
        }
        CP_COMMIT();

        const uint32_t sA = sbase + slot * STAGE_BYTES;
        const uint32_t sB = sA + BM * 128;
#pragma unroll
        for (int ks = 0; ks < 4; ks++) {
            uint32_t a[4][4];
#pragma unroll
            for (int i = 0; i < 4; i++) {
                const int row = rAb + i * 16;
                const uint32_t ad = sA + row * 128 + (((ks * 2 + cAdd) ^ (row & 7)) << 4);
                LDSM4(a[i][0], a[i][1], a[i][2], a[i][3], ad);
            }
            uint32_t b[4][2];
#pragma unroll
            for (int g = 0; g < 2; g++) {
                const int row = rBb + g * 16;
                const uint32_t bd = sB + row * 128 + (((ks * 2 + cBdd) ^ (row & 7)) << 4);
                uint32_t r0, r1, r2, r3;
                LDSM4(r0, r1, r2, r3, bd);
                b[2 * g + 0][0] = r0; b[2 * g + 0][1] = r1;
                b[2 * g + 1][0] = r2; b[2 * g + 1][1] = r3;
            }
#pragma unroll
            for (int i = 0; i < 4; i++)
#pragma unroll
                for (int j = 0; j < 4; j++)
                    MMA16816(acc[i][j][0], acc[i][j][1], acc[i][j][2], acc[i][j][3],
                             a[i][0], a[i][1], a[i][2], a[i][3],
                             b[j][0], b[j][1]);
        }
        slot = (slot + 1 == STAGES) ? 0 : slot + 1;
        wslot = (wslot + 1 == STAGES) ? 0 : wslot + 1;
    }

    const int qrow = lane >> 2;
    const int qcol = (lane & 3) * 2;
#pragma unroll
    for (int i = 0; i < 4; i++) {
        const int m0 = by * BM + wm + i * 16 + qrow;
#pragma unroll
        for (int j = 0; j < 4; j++) {
            const int n0 = bx * BN + wn + j * 8 + qcol;
            const float be0 = __ldg(be + n0), be1 = __ldg(be + n0 + 1);
            __nv_bfloat162 p0 = __floats2bfloat162_rn(acc[i][j][0] + be0, acc[i][j][1] + be1);
            __nv_bfloat162 p1 = __floats2bfloat162_rn(acc[i][j][2] + be0, acc[i][j][3] + be1);
            *(uint32_t*)(g_Pa + (size_t)m0 * H_ + n0)       = *(uint32_t*)&p0;
            *(uint32_t*)(g_Pa + (size_t)(m0 + 8) * H_ + n0) = *(uint32_t*)&p1;
        }
    }
}

// ---------------- topk select (approx): candidates -> global; zero sparse row ----------------
__global__ void __launch_bounds__(256) topk_kernel(float* __restrict__ sparse) {
    const int row = blockIdx.x;
    const int tid = threadIdx.x;
    __shared__ int hist[256];
    __shared__ int sfx[256];
    __shared__ unsigned bc_prefix;
    __shared__ int bc_r;
    __shared__ int warpOff[8];
    __shared__ int s_total;

    // load approx row as 16-bit monotone keys (48/thread)
    const uint4* rowPa = (const uint4*)(g_Pa + (size_t)row * H_);
    unsigned short keys[48];
#pragma unroll
    for (int jc = 0; jc < 6; jc++) {
        uint4 v = rowPa[tid + jc * 256];
        unsigned wd[4] = {v.x, v.y, v.z, v.w};
#pragma unroll
        for (int q = 0; q < 4; q++) {
#pragma unroll
            for (int hh = 0; hh < 2; hh++) {
                unsigned u = (wd[q] >> (hh * 16)) & 0xFFFFu;
                keys[jc * 8 + q * 2 + hh] =
                    (unsigned short)((u & 0x8000u) ? (~u & 0xFFFFu) : (u | 0x8000u));
            }
        }
    }

    // 2-pass radix select over 16-bit keys: threshold = MARGIN-th largest
    unsigned prefix = 0;
    int r = MARGIN;
#pragma unroll 1
    for (int p = 0; p < 2; p++) {
        const int shift = 8 - p * 8;
        hist[tid] = 0;
        __syncthreads();
#pragma unroll 1
        for (int j = 0; j < 48; j++) {
            unsigned k = keys[j];
            bool ok = (p == 0) || ((k >> 8) == prefix);
            unsigned active = __ballot_sync(0xFFFFFFFFu, ok);
            if (ok) {
                int bin = (k >> shift) & 255;
                unsigned mm = __match_any_sync(active, bin);
                if ((tid & 31) == (__ffs(mm) - 1)) atomicAdd(&hist[bin], __popc(mm));
            }
        }
        __syncthreads();
        sfx[tid] = hist[tid];
        __syncthreads();
        for (int off = 1; off < 256; off <<= 1) {
            int v = sfx[tid];
            int a = (tid + off < 256) ? sfx[tid + off] : 0;
            __syncthreads();
            sfx[tid] = v + a;
            __syncthreads();
        }
        int here = sfx[tid], above = (tid < 255) ? sfx[tid + 1] : 0;
        if (here >= r && above < r) { bc_prefix = (prefix << 8) | (unsigned)tid; bc_r = r - above; }
        __syncthreads();
        prefix = bc_prefix;
        r = bc_r;
        __syncthreads();
    }
    const unsigned T = prefix;

    // deterministic compaction of candidates (key >= T), cap CAND, to global
    unsigned long long selM = 0;
    int cnt = 0;
#pragma unroll 1
    for (int j = 0; j < 48; j++)
        if ((unsigned)keys[j] >= T) { selM |= 1ull << j; cnt++; }
    const int lane = tid & 31, w = tid >> 5;
    int incl = cnt;
    for (int off = 1; off < 32; off <<= 1) {
        int n = __shfl_up_sync(0xFFFFFFFFu, incl, off);
        if (lane >= off) incl += n;
    }
    if (lane == 31) warpOff[w] = incl;
    __syncthreads();
    if (tid == 0) {
        int s = 0;
        for (int a = 0; a < 8; a++) { int t = warpOff[a]; warpOff[a] = s; s += t; }
        s_total = s;
        g_candCnt[row] = s < CAND ? s : CAND;
    }
    __syncthreads();
    int pos = warpOff[w] + incl - cnt;
#pragma unroll 1
    for (int j = 0; j < 48; j++)
        if ((selM >> j) & 1ull) {
            if (pos < CAND) g_candIdx[row * CAND + pos] = (j >> 3) * 2048 + tid * 8 + (j & 7);
            pos++;
        }

    // zero sparse row (scatter happens in rescore_dec)
    float* rowp = sparse + (size_t)row * H_;
    const float4 z = make_float4(0.f, 0.f, 0.f, 0.f);
#pragma unroll
    for (int q = 0; q < 3; q++)
        ((float4*)rowp)[tid + q * 256] = z;
}

// ---------------- fused exact rescore + DECODE: 4 rows/block ----------------
__global__ void __launch_bounds__(256) rescore_dec(const float* __restrict__ x,
                                                   const float* __restrict__ We,
                                                   const float* __restrict__ be,
                                                   const float* __restrict__ bdec,
                                                   float* __restrict__ sparse,
                                                   float* __restrict__ xhat) {
    const int tid = threadIdx.x;
    const int sub = tid >> 6;          // 0..3: row within block
    const int ci  = tid & 63;          // candidate slot
    const int row = blockIdx.x * RPB + sub;

    __shared__ __align__(16) float xs[RPB][D_];
    __shared__ float cval[RPB][CAND];
    __shared__ int   cidx[RPB][CAND];
    __shared__ int   ccnt[RPB];
    __shared__ int   selIdx[RPB][K_];
    __shared__ float selVal[RPB][K_];

    // cooperative: centered x rows into smem (exact fp32, same op as reference)
    {
        const float4* br = (const float4*)bdec;
        for (int q = tid; q < RPB * (D_ / 4); q += 256) {
            const int rr = q / (D_ / 4), pp = q % (D_ / 4);
            float4 a = ((const float4*)(x + (size_t)(blockIdx.x * RPB + rr) * D_))[pp];
            float4 b = br[pp];
            a.x -= b.x; a.y -= b.y; a.z -= b.z; a.w -= b.w;
            *(float4*)(&xs[rr][pp * 4]) = a;
        }
    }
    // candidate lists (256 = RPB*CAND exactly)
    cidx[sub][ci] = g_candIdx[row * CAND + ci];
    if (ci == 0) ccnt[sub] = g_candCnt[row];
    __syncthreads();

    const int cnt = ccnt[sub];
    if (ci < cnt) {
        const int col = cidx[sub][ci];
        const float bias = __ldg(be + col);
        const float4* Wr = (const float4*)(We + (size_t)col * D_);
        float acc = 0.f;
#pragma unroll 8
        for (int q = 0; q < D_ / 4; q++) {
            float4 wv = __ldg(Wr + q);
            float4 xv = *(const float4*)(&xs[sub][q * 4]);
            acc = fmaf(xv.x, wv.x, acc);
            acc = fmaf(xv.y, wv.y, acc);
            acc = fmaf(xv.z, wv.z, acc);
            acc = fmaf(xv.w, wv.w, acc);
        }
        cval[sub][ci] = acc + bias;
    }
    __syncthreads();

    // exact ranking among this row's candidates; tie-break lowest index
    if (ci < cnt) {
        const float vi = cval[sub][ci];
        const int ii = cidx[sub][ci];
        int rank = 0;
        for (int j = 0; j < cnt; j++) {
            float vj = cval[sub][j];
            if (vj > vi || (vj == vi && cidx[sub][j] < ii)) rank++;
        }
        if (rank < K_) {
            const float rv = fmaxf(vi, 0.f);
            selIdx[sub][rank] = ii;
            selVal[sub][rank] = rv;
            sparse[(size_t)row * H_ + ii] = rv;   // row pre-zeroed by topk_kernel
        }
    }
    __syncthreads();

    // decode: same rank-order fmaf chain per output as the previous dec_kernel
    const float4* bd4 = (const float4*)bdec;
#pragma unroll 1
    for (int i = 0; i < RPB * (D_ / 4) / 256; i++) {   // 6 iterations
        const int o  = tid + i * 256;                  // 0..1535
        const int rr = o / (D_ / 4);
        const int p  = o % (D_ / 4);
        float4 acc = bd4[p];
#pragma unroll 8
        for (int k = 0; k < K_; k++) {
            const float v = selVal[rr][k];
            const float4 wv = *(const float4*)(g_WdT + (size_t)selIdx[rr][k] * D_ + p * 4);
            acc.x = fmaf(v, wv.x, acc.x);
            acc.y = fmaf(v, wv.y, acc.y);
            acc.z = fmaf(v, wv.z, acc.z);
            acc.w = fmaf(v, wv.w, acc.w);
        }
        *(float4*)(xhat + (size_t)(blockIdx.x * RPB + rr) * D_ + p * 4) = acc;
    }
}

// ---------------- launch ----------------
extern "C" void kernel_launch(void* const* d_in, const int* in_sizes, int n_in,
                              void* d_out, int out_size) {
    const float* x   = (const float*)d_in[0];
    const float* W_e = (const float*)d_in[1];
    const float* b_e = (const float*)d_in[2];
    const float* W_d = (const float*)d_in[3];
    const float* b_d = (const float*)d_in[4];
    float* out    = (float*)d_out;
    float* xhat   = out;                      // (B, D)
    float* sparse = out + (size_t)B_ * D_;    // (B, H)

    cudaFuncSetAttribute(enc_gemm, cudaFuncAttributeMaxDynamicSharedMemorySize,
                         STAGES * STAGE_BYTES);

    prep_x        <<<B_, 384>>>(x, b_d);
    prep_w        <<<H_, 384>>>(W_e);
    prep_transpose<<<dim3(H_ / 32, D_ / 32), dim3(32, 8)>>>(W_d);
    enc_gemm      <<<dim3(H_ / BN, B_ / BM), 256, STAGES * STAGE_BYTES>>>(b_e);
    topk_kernel   <<<B_, 256>>>(sparse);
    rescore_dec   <<<B_ / RPB, 256>>>(x, W_e, b_e, b_d, sparse, xhat);
}

// round 17
// speedup vs baseline: 1.0482x; 1.0482x over previous
#include <cuda_runtime.h>
#include <cuda_bf16.h>
#include <cstdint>

#define B_ 16384
#define D_ 1536
#define H_ 12288
#define K_ 32
#define MARGIN 36
#define CAND 64
#define RPB 4                           // rows per rescore block

#define BM 128
#define BN 128
#define BK 64
#define STAGES 3
#define NT (D_ / BK)                    // 24 k-tiles
#define STAGE_BYTES (BM * 128 + BN * 128)   // 32 KB (A 16KB + B 16KB)

// ---------------- static scratch ----------------
__device__ __align__(256) __nv_bfloat16 g_Xbf[(size_t)B_ * D_];  // centered x, bf16
__device__ __align__(256) __nv_bfloat16 g_Wbf[(size_t)H_ * D_];  // W_enc, bf16
__device__ __align__(256) __nv_bfloat16 g_Pa[(size_t)B_ * H_];   // approx preact, bf16
__device__ __align__(256) float g_WdT[(size_t)H_ * D_];          // W_dec^T (H,D)
__device__ int   g_tidx[B_ * K_];
__device__ float g_tval[B_ * K_];
__device__ int   g_candIdx[B_ * CAND];
__device__ int   g_candCnt[B_];

// ---------------- helpers ----------------
static __device__ __forceinline__ uint32_t smem_u32(const void* p) {
    uint32_t a;
    asm("{ .reg .u64 t; cvta.to.shared.u64 t, %1; cvt.u32.u64 %0, t; }" : "=r"(a) : "l"(p));
    return a;
}
#define CP16(dst, src) \
    asm volatile("cp.async.cg.shared.global [%0], [%1], 16;" :: "r"(dst), "l"(src) : "memory")
#define CP_COMMIT() asm volatile("cp.async.commit_group;" ::: "memory")
#define CP_WAIT1()  asm volatile("cp.async.wait_group 1;" ::: "memory")

#define LDSM4(r0, r1, r2, r3, a) \
    asm volatile("ldmatrix.sync.aligned.m8n8.x4.shared.b16 {%0,%1,%2,%3}, [%4];" \
                 : "=r"(r0), "=r"(r1), "=r"(r2), "=r"(r3) : "r"(a))

#define MMA16816(c0, c1, c2, c3, a0, a1, a2, a3, b0, b1) \
    asm volatile("mma.sync.aligned.m16n8k16.row.col.f32.bf16.bf16.f32 " \
                 "{%0,%1,%2,%3},{%4,%5,%6,%7},{%8,%9},{%0,%1,%2,%3};" \
                 : "+f"(c0), "+f"(c1), "+f"(c2), "+f"(c3) \
                 : "r"(a0), "r"(a1), "r"(a2), "r"(a3), "r"(b0), "r"(b1))

// ---------------- prep: x_centered -> bf16 ----------------
__global__ void __launch_bounds__(384) prep_x(const float* __restrict__ x,
                                              const float* __restrict__ bd) {
    int t = threadIdx.x;                       // 384 = D_/4
    size_t base = (size_t)blockIdx.x * D_;
    float4 xv = ((const float4*)(x + base))[t];
    float4 bv = ((const float4*)bd)[t];
    __nv_bfloat162 p0 = __floats2bfloat162_rn(xv.x - bv.x, xv.y - bv.y);
    __nv_bfloat162 p1 = __floats2bfloat162_rn(xv.z - bv.z, xv.w - bv.w);
    uint2 o;
    o.x = *(uint32_t*)&p0;
    o.y = *(uint32_t*)&p1;
    ((uint2*)(g_Xbf + base))[t] = o;
}

// ---------------- prep: W_enc -> bf16 ----------------
__global__ void __launch_bounds__(384) prep_w(const float* __restrict__ W) {
    int t = threadIdx.x;
    size_t base = (size_t)blockIdx.x * D_;
    float4 wv = ((const float4*)(W + base))[t];
    __nv_bfloat162 p0 = __floats2bfloat162_rn(wv.x, wv.y);
    __nv_bfloat162 p1 = __floats2bfloat162_rn(wv.z, wv.w);
    uint2 o;
    o.x = *(uint32_t*)&p0;
    o.y = *(uint32_t*)&p1;
    ((uint2*)(g_Wbf + base))[t] = o;
}

// ---------------- prep: transpose W_dec (D,H) -> (H,D) ----------------
__global__ void __launch_bounds__(256) prep_transpose(const float* __restrict__ Wd) {
    __shared__ float t[32][33];
    int h0 = blockIdx.x * 32, d0 = blockIdx.y * 32;
    int x = threadIdx.x, y = threadIdx.y;
#pragma unroll
    for (int j = 0; j < 32; j += 8)
        t[y + j][x] = Wd[(size_t)(d0 + y + j) * H_ + h0 + x];
    __syncthreads();
#pragma unroll
    for (int j = 0; j < 32; j += 8)
        g_WdT[(size_t)(h0 + y + j) * D_ + d0 + x] = t[x][y + j];
}

// ---------------- encoder GEMM (mma.sync bf16): approx preact ----------------
__global__ void __launch_bounds__(256, 2) enc_gemm(const float* __restrict__ be) {
    extern __shared__ char smem[];
    const uint32_t sbase = smem_u32(smem);
    const int tid = threadIdx.x;
    const int bx = blockIdx.x;   // N tile (96)
    const int by = blockIdx.y;   // M tile (128)
    const int lane = tid & 31, w = tid >> 5;
    const int wm = (w >> 2) * 64;
    const int wn = (w & 3) * 32;

    const int grow = tid >> 1;
    const int half = tid & 1;
    const __nv_bfloat16* Agp = g_Xbf + (size_t)(by * BM + grow) * D_;
    const __nv_bfloat16* Bgp = g_Wbf + (size_t)(bx * BN + grow) * D_;
    uint32_t dstOff[4];
#pragma unroll
    for (int i = 0; i < 4; i++) {
        const int c = half * 4 + i;
        dstOff[i] = grow * 128 + (((c) ^ (grow & 7)) << 4);
    }
    const int srcC = half * 4;

    const int rAb = wm + (lane & 7) + ((lane >> 3) & 1) * 8;
    const int cAdd = lane >> 4;
    const int rBb = wn + ((lane >> 4) & 1) * 8 + (lane & 7);
    const int cBdd = (lane >> 3) & 1;

    float acc[4][4][4];
#pragma unroll
    for (int i = 0; i < 4; i++)
#pragma unroll
        for (int j = 0; j < 4; j++)
#pragma unroll
            for (int q = 0; q < 4; q++) acc[i][j][q] = 0.f;

#pragma unroll
    for (int s = 0; s < STAGES - 1; s++) {
        const uint32_t sA = sbase + s * STAGE_BYTES;
        const uint32_t sB = sA + BM * 128;
        const __nv_bfloat16* a = Agp + s * BK + srcC * 8;
        const __nv_bfloat16* b = Bgp + s * BK + srcC * 8;
#pragma unroll
        for (int i = 0; i < 4; i++) {
            CP16(sA + dstOff[i], a + i * 8);
            CP16(sB + dstOff[i], b + i * 8);
        }
        CP_COMMIT();
    }

    int slot = 0, wslot = STAGES - 1;
    for (int kt = 0; kt < NT; kt++) {
        CP_WAIT1();
        __syncthreads();

        if (kt + STAGES - 1 < NT) {
            const uint32_t sA = sbase + wslot * STAGE_BYTES;
            const uint32_t sB = sA + BM * 128;
            const __nv_bfloat16* a = Agp + (kt + STAGES - 1) * BK + srcC * 8;
            const __nv_bfloat16* b = Bgp + (kt + STAGES - 1) * BK + srcC * 8;
#pragma unroll
            for (int i = 0; i < 4; i++) {
                CP16(sA + dstOff[i], a + i * 8);
                CP16(sB + dstOff[i], b + i * 8);
            }
        }
        CP_COMMIT();

        const uint32_t sA = sbase + slot * STAGE_BYTES;
        const uint32_t sB = sA + BM * 128;
#pragma unroll
        for (int ks = 0; ks < 4; ks++) {
            uint32_t a[4][4];
#pragma unroll
            for (int i = 0; i < 4; i++) {
                const int row = rAb + i * 16;
                const uint32_t ad = sA + row * 128 + (((ks * 2 + cAdd) ^ (row & 7)) << 4);
                LDSM4(a[i][0], a[i][1], a[i][2], a[i][3], ad);
            }
            uint32_t b[4][2];
#pragma unroll
            for (int g = 0; g < 2; g++) {
                const int row = rBb + g * 16;
                const uint32_t bd = sB + row * 128 + (((ks * 2 + cBdd) ^ (row & 7)) << 4);
                uint32_t r0, r1, r2, r3;
                LDSM4(r0, r1, r2, r3, bd);
                b[2 * g + 0][0] = r0; b[2 * g + 0][1] = r1;
                b[2 * g + 1][0] = r2; b[2 * g + 1][1] = r3;
            }
#pragma unroll
            for (int i = 0; i < 4; i++)
#pragma unroll
                for (int j = 0; j < 4; j++)
                    MMA16816(acc[i][j][0], acc[i][j][1], acc[i][j][2], acc[i][j][3],
                             a[i][0], a[i][1], a[i][2], a[i][3],
                             b[j][0], b[j][1]);
        }
        slot = (slot + 1 == STAGES) ? 0 : slot + 1;
        wslot = (wslot + 1 == STAGES) ? 0 : wslot + 1;
    }

    const int qrow = lane >> 2;
    const int qcol = (lane & 3) * 2;
#pragma unroll
    for (int i = 0; i < 4; i++) {
        const int m0 = by * BM + wm + i * 16 + qrow;
#pragma unroll
        for (int j = 0; j < 4; j++) {
            const int n0 = bx * BN + wn + j * 8 + qcol;
            const float be0 = __ldg(be + n0), be1 = __ldg(be + n0 + 1);
            __nv_bfloat162 p0 = __floats2bfloat162_rn(acc[i][j][0] + be0, acc[i][j][1] + be1);
            __nv_bfloat162 p1 = __floats2bfloat162_rn(acc[i][j][2] + be0, acc[i][j][3] + be1);
            *(uint32_t*)(g_Pa + (size_t)m0 * H_ + n0)       = *(uint32_t*)&p0;
            *(uint32_t*)(g_Pa + (size_t)(m0 + 8) * H_ + n0) = *(uint32_t*)&p1;
        }
    }
}

// ---------------- topk select (approx): candidates -> global; zero sparse row ----------------
__global__ void __launch_bounds__(256) topk_kernel(float* __restrict__ sparse) {
    const int row = blockIdx.x;
    const int tid = threadIdx.x;
    __shared__ int hist[256];
    __shared__ unsigned bc_prefix;
    __shared__ int bc_r;
    __shared__ int warpOff[8];
    __shared__ int warpTot[8];
    __shared__ int warpAbove[8];
    __shared__ int s_total;

    const int lane = tid & 31, w = tid >> 5;

    // load approx row as 16-bit monotone keys (48/thread)
    const uint4* rowPa = (const uint4*)(g_Pa + (size_t)row * H_);
    unsigned short keys[48];
#pragma unroll
    for (int jc = 0; jc < 6; jc++) {
        uint4 v = rowPa[tid + jc * 256];
        unsigned wd[4] = {v.x, v.y, v.z, v.w};
#pragma unroll
        for (int q = 0; q < 4; q++) {
#pragma unroll
            for (int hh = 0; hh < 2; hh++) {
                unsigned u = (wd[q] >> (hh * 16)) & 0xFFFFu;
                keys[jc * 8 + q * 2 + hh] =
                    (unsigned short)((u & 0x8000u) ? (~u & 0xFFFFu) : (u | 0x8000u));
            }
        }
    }

    // 2-pass radix select over 16-bit keys: threshold = MARGIN-th largest
    unsigned prefix = 0;
    int r = MARGIN;
#pragma unroll 1
    for (int p = 0; p < 2; p++) {
        const int shift = 8 - p * 8;
        hist[tid] = 0;
        __syncthreads();
#pragma unroll 1
        for (int j = 0; j < 48; j++) {
            unsigned k = keys[j];
            bool ok = (p == 0) || ((k >> 8) == prefix);
            unsigned active = __ballot_sync(0xFFFFFFFFu, ok);
            if (ok) {
                int bin = (k >> shift) & 255;
                unsigned mm = __match_any_sync(active, bin);
                if ((tid & 31) == (__ffs(mm) - 1)) atomicAdd(&hist[bin], __popc(mm));
            }
        }
        __syncthreads();
        // warp-shuffle suffix scan (sfx[i] = sum_{j>=i} hist[j])
        int val = hist[tid];
#pragma unroll
        for (int off = 1; off < 32; off <<= 1) {
            int n = __shfl_down_sync(0xFFFFFFFFu, val, off);
            if (lane + off < 32) val += n;
        }
        if (lane == 0) warpTot[w] = val;   // warp total (suffix at lane 0)
        __syncthreads();
        if (tid < 8) {
            int s = 0;
            for (int j = tid + 1; j < 8; j++) s += warpTot[j];
            warpAbove[tid] = s;            // suffix of warps strictly after w
        }
        __syncthreads();
        const int here = val + warpAbove[w];
        int above = __shfl_down_sync(0xFFFFFFFFu, here, 1);
        if (lane == 31) above = warpAbove[w];
        if (here >= r && above < r) { bc_prefix = (prefix << 8) | (unsigned)tid; bc_r = r - above; }
        __syncthreads();
        prefix = bc_prefix;
        r = bc_r;
        __syncthreads();
    }
    const unsigned T = prefix;

    // deterministic compaction of candidates (key >= T), cap CAND, to global
    unsigned long long selM = 0;
    int cnt = 0;
#pragma unroll 1
    for (int j = 0; j < 48; j++)
        if ((unsigned)keys[j] >= T) { selM |= 1ull << j; cnt++; }
    int incl = cnt;
    for (int off = 1; off < 32; off <<= 1) {
        int n = __shfl_up_sync(0xFFFFFFFFu, incl, off);
        if (lane >= off) incl += n;
    }
    if (lane == 31) warpOff[w] = incl;
    __syncthreads();
    if (tid == 0) {
        int s = 0;
        for (int a = 0; a < 8; a++) { int t = warpOff[a]; warpOff[a] = s; s += t; }
        s_total = s;
        g_candCnt[row] = s < CAND ? s : CAND;
    }
    __syncthreads();
    int pos = warpOff[w] + incl - cnt;
#pragma unroll 1
    for (int j = 0; j < 48; j++)
        if ((selM >> j) & 1ull) {
            if (pos < CAND) g_candIdx[row * CAND + pos] = (j >> 3) * 2048 + tid * 8 + (j & 7);
            pos++;
        }

    // zero sparse row (scatter happens in rescore_kernel)
    float* rowp = sparse + (size_t)row * H_;
    const float4 z = make_float4(0.f, 0.f, 0.f, 0.f);
#pragma unroll
    for (int q = 0; q < 3; q++)
        ((float4*)rowp)[tid + q * 256] = z;
}

// ---------------- exact rescore: 4 rows/block, 1 thread/candidate ----------------
__global__ void __launch_bounds__(256) rescore_kernel(const float* __restrict__ x,
                                                      const float* __restrict__ We,
                                                      const float* __restrict__ be,
                                                      const float* __restrict__ bdec,
                                                      float* __restrict__ sparse) {
    const int tid = threadIdx.x;
    const int sub = tid >> 6;          // 0..3: row within block
    const int ci  = tid & 63;          // candidate slot
    const int row = blockIdx.x * RPB + sub;

    __shared__ __align__(16) float xs[RPB][D_];
    __shared__ float cval[RPB][CAND];
    __shared__ int   cidx[RPB][CAND];
    __shared__ int   ccnt[RPB];

    // cooperative: centered x rows into smem (exact fp32, same op as reference)
    {
        const float4* br = (const float4*)bdec;
        for (int q = tid; q < RPB * (D_ / 4); q += 256) {
            const int rr = q / (D_ / 4), pp = q % (D_ / 4);
            float4 a = ((const float4*)(x + (size_t)(blockIdx.x * RPB + rr) * D_))[pp];
            float4 b = br[pp];
            a.x -= b.x; a.y -= b.y; a.z -= b.z; a.w -= b.w;
            *(float4*)(&xs[rr][pp * 4]) = a;
        }
    }
    // candidate lists (256 = RPB*CAND exactly)
    cidx[sub][ci] = g_candIdx[row * CAND + ci];
    if (ci == 0) ccnt[sub] = g_candCnt[row];
    __syncthreads();

    const int cnt = ccnt[sub];
    if (ci < cnt) {
        const int col = cidx[sub][ci];
        const float bias = __ldg(be + col);
        const float4* Wr = (const float4*)(We + (size_t)col * D_);
        float acc = 0.f;
#pragma unroll 8
        for (int q = 0; q < D_ / 4; q++) {
            float4 wv = __ldg(Wr + q);
            float4 xv = *(const float4*)(&xs[sub][q * 4]);
            acc = fmaf(xv.x, wv.x, acc);
            acc = fmaf(xv.y, wv.y, acc);
            acc = fmaf(xv.z, wv.z, acc);
            acc = fmaf(xv.w, wv.w, acc);
        }
        cval[sub][ci] = acc + bias;
    }
    __syncthreads();

    // exact ranking among this row's candidates; tie-break lowest index
    if (ci < cnt) {
        const float vi = cval[sub][ci];
        const int ii = cidx[sub][ci];
        int rank = 0;
        for (int j = 0; j < cnt; j++) {
            float vj = cval[sub][j];
            if (vj > vi || (vj == vi && cidx[sub][j] < ii)) rank++;
        }
        if (rank < K_) {
            const float rv = fmaxf(vi, 0.f);
            g_tidx[row * K_ + rank] = ii;
            g_tval[row * K_ + rank] = rv;
            sparse[(size_t)row * H_ + ii] = rv;   // row pre-zeroed by topk_kernel
        }
    }
}

// ---------------- decode: x_hat = sparse @ W_dec^T + b_dec ----------------
__global__ void __launch_bounds__(384) dec_kernel(const float* __restrict__ b_dec,
                                                  float* __restrict__ xhat) {
    const int row = blockIdx.x, tid = threadIdx.x;
    __shared__ int   sidx[K_];
    __shared__ float sval[K_];
    if (tid < K_) {
        sidx[tid] = g_tidx[row * K_ + tid];
        sval[tid] = g_tval[row * K_ + tid];
    }
    __syncthreads();
    float4 acc = ((const float4*)b_dec)[tid];
#pragma unroll 8
    for (int k = 0; k < K_; k++) {
        float v = sval[k];
        float4 wv = *(const float4*)(g_WdT + (size_t)sidx[k] * D_ + tid * 4);
        acc.x += v * wv.x; acc.y += v * wv.y;
        acc.z += v * wv.z; acc.w += v * wv.w;
    }
    *(float4*)(xhat + (size_t)row * D_ + tid * 4) = acc;
}

// ---------------- launch ----------------
extern "C" void kernel_launch(void* const* d_in, const int* in_sizes, int n_in,
                              void* d_out, int out_size) {
    const float* x   = (const float*)d_in[0];
    const float* W_e = (const float*)d_in[1];
    const float* b_e = (const float*)d_in[2];
    const float* W_d = (const float*)d_in[3];
    const float* b_d = (const float*)d_in[4];
    float* out    = (float*)d_out;
    float* xhat   = out;                      // (B, D)
    float* sparse = out + (size_t)B_ * D_;    // (B, H)

    cudaFuncSetAttribute(enc_gemm, cudaFuncAttributeMaxDynamicSharedMemorySize,
                         STAGES * STAGE_BYTES);

    prep_x        <<<B_, 384>>>(x, b_d);
    prep_w        <<<H_, 384>>>(W_e);
    prep_transpose<<<dim3(H_ / 32, D_ / 32), dim3(32, 8)>>>(W_d);
    enc_gemm      <<<dim3(H_ / BN, B_ / BM), 256, STAGES * STAGE_BYTES>>>(b_e);
    topk_kernel   <<<B_, 256>>>(sparse);
    rescore_kernel<<<B_ / RPB, 256>>>(x, W_e, b_e, b_d, sparse);
    dec_kernel    <<<B_, 384>>>(b_d, xhat);
}